// round 5
// baseline (speedup 1.0000x reference)
#include <cuda_runtime.h>
#include <cuda_bf16.h>
#include <math.h>
#include <stdint.h>

#define TSTEPS 5
#define BATCH  128
#define IN0    512
#define HID    1024
#define G4     4096
#define OUTD   32

// bulk GEMM tiles (XG kernels)
#define BM 128
#define BN 128
#define BK 32
#define NTH 256
#define RS 40            // smem row stride in bf16 (32 data + 8 pad)

// fused step kernel
#define SBM 32           // batch rows per CTA
#define RSF 132          // epilogue smem fp32 row stride
// dyn smem layout: sA[buf][hi/lo] 32x40x2B, sW[buf][hi/lo] 128x40x2B
#define SA_ONE   2560
#define SA_TOT   10240                      // 2 bufs * 2 copies
#define SW_ONE   10240
#define SW_TOT   40960
#define DSMEM    (SA_TOT + SW_TOT)          // 51200

// Scratch (device globals; no allocations allowed)
__device__ float g_xg0[TSTEPS * BATCH * G4];
__device__ float g_xg1[TSTEPS * BATCH * G4];
__device__ float g_h1 [TSTEPS * BATCH * HID];
__device__ float g_h2 [TSTEPS * BATCH * HID];
__device__ float g_c  [BATCH * HID];
__device__ __nv_bfloat16 g_hhi[2][BATCH * HID];
__device__ __nv_bfloat16 g_hlo[2][BATCH * HID];
__device__ __nv_bfloat16 g_wghi[2][G4 * HID];   // gathered: [blk32][g*32+ui][k]
__device__ __nv_bfloat16 g_wglo[2][G4 * HID];

__device__ __forceinline__ uint32_t smem_u32(const void* p) {
    uint32_t a;
    asm("{ .reg .u64 t; cvta.to.shared.u64 t, %1; cvt.u32.u64 %0, t; }"
        : "=r"(a) : "l"(p));
    return a;
}

#define LDSM_X4(R, addr)                                                     \
    asm volatile("ldmatrix.sync.aligned.m8n8.x4.shared.b16 "                 \
                 "{%0,%1,%2,%3}, [%4];"                                      \
                 : "=r"((R)[0]), "=r"((R)[1]), "=r"((R)[2]), "=r"((R)[3])    \
                 : "r"(addr))
#define LDSM_X2(R, addr)                                                     \
    asm volatile("ldmatrix.sync.aligned.m8n8.x2.shared.b16 {%0,%1}, [%2];"   \
                 : "=r"((R)[0]), "=r"((R)[1]) : "r"(addr))
#define MMA_BF16(D, Ar, Br)                                                  \
    asm volatile("mma.sync.aligned.m16n8k16.row.col.f32.bf16.bf16.f32 "      \
                 "{%0,%1,%2,%3}, {%4,%5,%6,%7}, {%8,%9}, {%0,%1,%2,%3};"     \
                 : "+f"((D)[0]), "+f"((D)[1]), "+f"((D)[2]), "+f"((D)[3])    \
                 : "r"((Ar)[0]), "r"((Ar)[1]), "r"((Ar)[2]), "r"((Ar)[3]),   \
                   "r"((Br)[0]), "r"((Br)[1]))

__device__ __forceinline__ void split_bf16(float f, uint16_t& h, uint16_t& l) {
    __nv_bfloat16 hb = __float2bfloat16(f);
    __nv_bfloat16 lb = __float2bfloat16(f - __bfloat162float(hb));
    h = __bfloat16_as_ushort(hb);
    l = __bfloat16_as_ushort(lb);
}
__device__ __forceinline__ float sigf(float x) { return 1.f / (1.f + expf(-x)); }

// ---------------------------------------------------------------------------
// Prep: split + gather Whh (both layers) into bf16 hi/lo.
// Gathered layout: dst[(bx*128 + g*32 + ui) * HID + k] = Whh[g*1024 + bx*32 + ui][k]
// ---------------------------------------------------------------------------
__global__ __launch_bounds__(256) void prep_whh(
    const float* __restrict__ w0, const float* __restrict__ w1)
{
    const int blk   = blockIdx.x;          // 0..63
    const int layer = blk >> 5;
    const int bx    = blk & 31;
    const float* W = layer ? w1 : w0;
    __nv_bfloat16* hi = g_wghi[layer];
    __nv_bfloat16* lo = g_wglo[layer];

    for (int i = threadIdx.x; i < 128 * 256; i += 256) {
        int r  = i >> 8;                   // 0..127 gathered row
        int c4 = (i & 255) * 4;
        int grow = (r >> 5) * HID + bx * 32 + (r & 31);
        float4 f = *(const float4*)(W + (size_t)grow * HID + c4);
        float fv[4] = {f.x, f.y, f.z, f.w};
        uint16_t h[4], l[4];
#pragma unroll
        for (int j = 0; j < 4; j++) split_bf16(fv[j], h[j], l[j]);
        size_t o = (size_t)(bx * 128 + r) * HID + c4;
        *(uint2*)(hi + o) = *(uint2*)h;
        *(uint2*)(lo + o) = *(uint2*)l;
    }
}

// ---------------------------------------------------------------------------
// Bulk tensor-core GEMM (XG precompute): C = A[M,K] @ W[N,K]^T + b1 + b2
// (unchanged from R3/R4 — proven)
// ---------------------------------------------------------------------------
__global__ __launch_bounds__(NTH) void hmma_gemm(
    const float* __restrict__ A, const float* __restrict__ W,
    int strideA, int strideW, int ksize,
    const float* __restrict__ b1, const float* __restrict__ b2,
    float* __restrict__ C, int ldc)
{
    __shared__ uint16_t sA[2][BM * RS];
    __shared__ uint16_t sW[2][BN * RS];

    const int tid  = threadIdx.x;
    const int lane = tid & 31;
    const int warp = tid >> 5;
    const int wm   = warp >> 2;
    const int wn   = warp & 3;
    const int row0 = blockIdx.y * BM;
    const int col0 = blockIdx.x * BN;
    const int nch  = ksize / BK;

    const bool isA = (tid < 128);
    const int  t2  = tid & 127;
    const float* src = isA ? (A + (size_t)row0 * strideA)
                           : (W + (size_t)col0 * strideW);
    const int sstr = isA ? strideA : strideW;
    uint16_t* d0 = isA ? sA[0] : sW[0];
    uint16_t* d1 = isA ? sA[1] : sW[1];

    float4 pf[8];
    const uint32_t bA0 = smem_u32(sA[0]);
    const uint32_t bA1 = smem_u32(sA[1]);
    const uint32_t bW0 = smem_u32(sW[0]);
    const uint32_t bW1 = smem_u32(sW[1]);

    float acc[4][4][4];
#pragma unroll
    for (int i = 0; i < 4; i++)
#pragma unroll
        for (int j = 0; j < 4; j++)
#pragma unroll
            for (int v = 0; v < 4; v++) acc[i][j][v] = 0.f;

#pragma unroll
    for (int i = 0; i < 8; i++) {
        int idx = t2 + 128 * i;
        int r = idx >> 3, c4 = idx & 7;
        pf[i] = *(const float4*)(src + (size_t)r * sstr + c4 * 4);
    }

    const int rl  = lane & 7;
    const int s8  = (lane >> 3) & 1;
    const int s16 = (lane >> 4) & 1;

    for (int c = 0; c < nch; c++) {
#pragma unroll
        for (int i = 0; i < 8; i++) {
            int idx = t2 + 128 * i;
            int r = idx >> 3, c4 = idx & 7;
            float f[4] = {pf[i].x, pf[i].y, pf[i].z, pf[i].w};
            uint16_t h[4], l[4];
#pragma unroll
            for (int j = 0; j < 4; j++) split_bf16(f[j], h[j], l[j]);
            int o = r * RS + c4 * 4;
            *(uint2*)(d0 + o) = *(uint2*)h;
            *(uint2*)(d1 + o) = *(uint2*)l;
        }
        __syncthreads();

        if (c + 1 < nch) {
            const int kk = (c + 1) * BK;
#pragma unroll
            for (int i = 0; i < 8; i++) {
                int idx = t2 + 128 * i;
                int r = idx >> 3, c4 = idx & 7;
                pf[i] = *(const float4*)(src + (size_t)r * sstr + kk + c4 * 4);
            }
        }

#pragma unroll
        for (int ks = 0; ks < 2; ks++) {
            const int k0b = (ks * 16 + s8 * 8) * 2;
            const int k0a = (ks * 16 + s16 * 8) * 2;
            uint32_t bh[4][2], bl[4][2];
#pragma unroll
            for (int nt = 0; nt < 4; nt++) {
                uint32_t ro = (uint32_t)(wn * 32 + nt * 8 + rl) * (RS * 2) + k0b;
                LDSM_X2(bh[nt], bW0 + ro);
                LDSM_X2(bl[nt], bW1 + ro);
            }
#pragma unroll
            for (int mt = 0; mt < 4; mt++) {
                uint32_t ro = (uint32_t)(wm * 64 + mt * 16 + rl + s8 * 8) * (RS * 2) + k0a;
                uint32_t ah[4], al[4];
                LDSM_X4(ah, bA0 + ro);
                LDSM_X4(al, bA1 + ro);
#pragma unroll
                for (int nt = 0; nt < 4; nt++) {
                    MMA_BF16(acc[mt][nt], ah, bh[nt]);
                    MMA_BF16(acc[mt][nt], ah, bl[nt]);
                    MMA_BF16(acc[mt][nt], al, bh[nt]);
                }
            }
        }
        __syncthreads();
    }

#pragma unroll
    for (int mt = 0; mt < 4; mt++) {
        int row = row0 + wm * 64 + mt * 16 + (lane >> 2);
#pragma unroll
        for (int nt = 0; nt < 4; nt++) {
            int col = col0 + wn * 32 + nt * 8 + (lane & 3) * 2;
            float bb0 = b1[col] + b2[col];
            float bb1 = b1[col + 1] + b2[col + 1];
            float2 v0 = make_float2(acc[mt][nt][0] + bb0, acc[mt][nt][1] + bb1);
            float2 v1 = make_float2(acc[mt][nt][2] + bb0, acc[mt][nt][3] + bb1);
            *(float2*)(C + (size_t)row * ldc + col) = v0;
            *(float2*)(C + (size_t)(row + 8) * ldc + col) = v1;
        }
    }
}

// ---------------------------------------------------------------------------
// gates0: t=0 step (no recurrent term). Writes c, h fp32, h hi/lo bf16.
// ---------------------------------------------------------------------------
__global__ __launch_bounds__(256) void gates0(
    const float* __restrict__ xg, float* __restrict__ hseq,
    __nv_bfloat16* __restrict__ hhi, __nv_bfloat16* __restrict__ hlo)
{
    int q  = blockIdx.x * 256 + threadIdx.x;   // 0..32767
    int b  = q >> 8;
    int j4 = (q & 255) * 4;
    size_t base = (size_t)b * G4 + j4;

    float4 xi = *(const float4*)(xg + base);
    float4 xf = *(const float4*)(xg + base + HID);
    float4 xc = *(const float4*)(xg + base + 2 * HID);
    float4 xo = *(const float4*)(xg + base + 3 * HID);

    float gi[4] = {xi.x, xi.y, xi.z, xi.w};
    float gf[4] = {xf.x, xf.y, xf.z, xf.w};
    float gc[4] = {xc.x, xc.y, xc.z, xc.w};
    float go[4] = {xo.x, xo.y, xo.z, xo.w};
    float cv[4], hv[4];
    uint16_t hh[4], hl[4];
#pragma unroll
    for (int j = 0; j < 4; j++) {
        cv[j] = sigf(gi[j]) * tanhf(gc[j]);            // cprev = 0; sig(f)*0
        hv[j] = sigf(go[j]) * tanhf(cv[j]);
        split_bf16(hv[j], hh[j], hl[j]);
    }
    int idx = b * HID + j4;
    *(float4*)(g_c + idx)  = make_float4(cv[0], cv[1], cv[2], cv[3]);
    *(float4*)(hseq + idx) = make_float4(hv[0], hv[1], hv[2], hv[3]);
    *(uint2*)(hhi + idx) = *(uint2*)hh;
    *(uint2*)(hlo + idx) = *(uint2*)hl;
}

// ---------------------------------------------------------------------------
// Fused recurrent step: one launch per timestep.
// grid = (32 unit-blocks, 4 batch-quarters). CTA computes gathered 32x128 tile
// (all 4 gates of its 32 units), applies LSTM gates inline.
// ---------------------------------------------------------------------------
__global__ __launch_bounds__(256) void lstm_step(
    const __nv_bfloat16* __restrict__ wg_hi,
    const __nv_bfloat16* __restrict__ wg_lo,
    const float* __restrict__ xgt,               // [BATCH][G4] slice for t
    const __nv_bfloat16* __restrict__ hp_hi,
    const __nv_bfloat16* __restrict__ hp_lo,
    __nv_bfloat16* __restrict__ ho_hi,
    __nv_bfloat16* __restrict__ ho_lo,
    float* __restrict__ hseq)                    // fp32 h for this t
{
    extern __shared__ char smem[];
    const int tid  = threadIdx.x;
    const int lane = tid & 31;
    const int warp = tid >> 5;
    const int wm   = warp >> 2;                 // 0..1 (16-row halves)
    const int wn   = warp & 3;                  // 0..3 (32-col groups)
    const int bx   = blockIdx.x;                // unit block (32 units)
    const int row0 = blockIdx.y * SBM;          // batch rows

    const uint32_t sb = smem_u32(smem);
    // sA(buf,copy) @ buf*5120 + copy*2560 ; sW(buf,copy) @ 10240 + buf*20480 + copy*10240

    const __nv_bfloat16* wbase_h = wg_hi + (size_t)bx * 128 * HID;
    const __nv_bfloat16* wbase_l = wg_lo + (size_t)bx * 128 * HID;

    const int rl  = lane & 7;
    const int s8  = (lane >> 3) & 1;
    const int s16 = (lane >> 4) & 1;

    float acc[4][4];
#pragma unroll
    for (int i = 0; i < 4; i++)
#pragma unroll
        for (int v = 0; v < 4; v++) acc[i][v] = 0.f;

    // prefetch assignments
    const bool isHi = (tid < 128);
    const int  t2   = tid & 127;
    const int  arr  = t2 >> 2, aseg = t2 & 3;   // A: 32 rows x 4 segs
    uint4 pA, pW[2][2];                         // pW[copy][v]

    // chunk 0
    {
        const __nv_bfloat16* hsrc = isHi ? hp_hi : hp_lo;
        pA = *(const uint4*)(hsrc + (size_t)(row0 + arr) * HID + aseg * 8);
#pragma unroll
        for (int wv = 0; wv < 2; wv++) {
            int idx = tid + 256 * wv;
            int r = idx >> 2, seg = idx & 3;
            pW[0][wv] = *(const uint4*)(wbase_h + (size_t)r * HID + seg * 8);
            pW[1][wv] = *(const uint4*)(wbase_l + (size_t)r * HID + seg * 8);
        }
    }

    for (int c = 0; c < HID / BK; c++) {
        const int buf = c & 1;
        // store prefetched chunk
        {
            char* sa = smem + buf * (2 * SA_ONE) + (isHi ? 0 : SA_ONE);
            *(uint4*)(sa + arr * (RS * 2) + aseg * 16) = pA;
            char* sw = smem + SA_TOT + buf * (2 * SW_ONE);
#pragma unroll
            for (int wv = 0; wv < 2; wv++) {
                int idx = tid + 256 * wv;
                int r = idx >> 2, seg = idx & 3;
                *(uint4*)(sw + r * (RS * 2) + seg * 16) = pW[0][wv];
                *(uint4*)(sw + SW_ONE + r * (RS * 2) + seg * 16) = pW[1][wv];
            }
        }
        __syncthreads();

        // prefetch next chunk
        if (c + 1 < HID / BK) {
            const int kk = (c + 1) * BK;
            const __nv_bfloat16* hsrc = isHi ? hp_hi : hp_lo;
            pA = *(const uint4*)(hsrc + (size_t)(row0 + arr) * HID + kk + aseg * 8);
#pragma unroll
            for (int wv = 0; wv < 2; wv++) {
                int idx = tid + 256 * wv;
                int r = idx >> 2, seg = idx & 3;
                pW[0][wv] = *(const uint4*)(wbase_h + (size_t)r * HID + kk + seg * 8);
                pW[1][wv] = *(const uint4*)(wbase_l + (size_t)r * HID + kk + seg * 8);
            }
        }

        const uint32_t aB0 = sb + buf * (2 * SA_ONE);
        const uint32_t aB1 = aB0 + SA_ONE;
        const uint32_t wB0 = sb + SA_TOT + buf * (2 * SW_ONE);
        const uint32_t wB1 = wB0 + SW_ONE;
#pragma unroll
        for (int ks = 0; ks < 2; ks++) {
            const int ka = (ks * 16 + s16 * 8) * 2;
            const int kb = (ks * 16 + s8 * 8) * 2;
            uint32_t ah[4], al[4];
            uint32_t ro = (uint32_t)(wm * 16 + rl + s8 * 8) * (RS * 2) + ka;
            LDSM_X4(ah, aB0 + ro);
            LDSM_X4(al, aB1 + ro);
#pragma unroll
            for (int nt = 0; nt < 4; nt++) {
                uint32_t rw = (uint32_t)(wn * 32 + nt * 8 + rl) * (RS * 2) + kb;
                uint32_t bh[2], bl[2];
                LDSM_X2(bh, wB0 + rw);
                LDSM_X2(bl, wB1 + rw);
                MMA_BF16(acc[nt], ah, bh);
                MMA_BF16(acc[nt], ah, bl);
                MMA_BF16(acc[nt], al, bh);
            }
        }
        __syncthreads();
    }

    // ---- epilogue: acc -> smem, fused gates ----
    float* sf = (float*)smem;                   // [32][RSF]
    {
        int row = wm * 16 + (lane >> 2);
#pragma unroll
        for (int nt = 0; nt < 4; nt++) {
            int cc = wn * 32 + nt * 8 + (lane & 3) * 2;
            sf[row * RSF + cc]            = acc[nt][0];
            sf[row * RSF + cc + 1]        = acc[nt][1];
            sf[(row + 8) * RSF + cc]      = acc[nt][2];
            sf[(row + 8) * RSF + cc + 1]  = acc[nt][3];
        }
    }
    __syncthreads();

#pragma unroll
    for (int i = 0; i < 4; i++) {
        int p    = tid + 256 * i;               // 0..1023
        int prow = p >> 5;                      // 0..31
        int ui   = p & 31;
        int j    = bx * 32 + ui;
        int grow = row0 + prow;
        size_t xb = (size_t)grow * G4 + j;
        float gi = sf[prow * RSF + ui]      + xgt[xb];
        float gf = sf[prow * RSF + 32 + ui] + xgt[xb + HID];
        float gg = sf[prow * RSF + 64 + ui] + xgt[xb + 2 * HID];
        float go = sf[prow * RSF + 96 + ui] + xgt[xb + 3 * HID];
        int idx = grow * HID + j;
        float cp = g_c[idx];
        float cn = sigf(gf) * cp + sigf(gi) * tanhf(gg);
        float hn = sigf(go) * tanhf(cn);
        g_c[idx]  = cn;
        hseq[idx] = hn;
        uint16_t hh, hl;
        split_bf16(hn, hh, hl);
        ho_hi[idx] = __ushort_as_bfloat16(hh);
        ho_lo[idx] = __ushort_as_bfloat16(hl);
    }
}

// ---------------------------------------------------------------------------
// Head: out[b,o] = dot(h2[4][b,:], Wout[o,:]) + bout[o]
// ---------------------------------------------------------------------------
__global__ __launch_bounds__(256) void head_kernel(
    const float* __restrict__ hfin,
    const float* __restrict__ Wout, const float* __restrict__ bout,
    float* __restrict__ out)
{
    __shared__ float hs[HID];
    __shared__ float red[8][32];
    int b = blockIdx.x;
    for (int i = threadIdx.x; i < HID; i += 256) hs[i] = hfin[(size_t)b * HID + i];
    __syncthreads();

    int o     = threadIdx.x % 32;
    int chunk = threadIdx.x / 32;
    float s = 0.f;
    const float* wrow = Wout + (size_t)o * HID;
#pragma unroll 4
    for (int k = chunk * 128; k < chunk * 128 + 128; k++)
        s = fmaf(hs[k], wrow[k], s);
    red[chunk][o] = s;
    __syncthreads();

    if (threadIdx.x < 32) {
        float t = 0.f;
#pragma unroll
        for (int ch = 0; ch < 8; ch++) t += red[ch][threadIdx.x];
        out[(size_t)b * OUTD + threadIdx.x] = t + bout[threadIdx.x];
    }
}

// ---------------------------------------------------------------------------
// Host launcher (14 kernel launches)
// ---------------------------------------------------------------------------
extern "C" void kernel_launch(void* const* d_in, const int* in_sizes, int n_in,
                              void* d_out, int out_size)
{
    const float* input = (const float*)d_in[0];
    const float* w_ih0 = (const float*)d_in[1];
    const float* w_hh0 = (const float*)d_in[2];
    const float* b_ih0 = (const float*)d_in[3];
    const float* b_hh0 = (const float*)d_in[4];
    const float* w_ih1 = (const float*)d_in[5];
    const float* w_hh1 = (const float*)d_in[6];
    const float* b_ih1 = (const float*)d_in[7];
    const float* b_hh1 = (const float*)d_in[8];
    const float* w_out = (const float*)d_in[9];
    const float* b_out = (const float*)d_in[10];
    float* out = (float*)d_out;

    cudaFuncSetAttribute(lstm_step,
                         cudaFuncAttributeMaxDynamicSharedMemorySize, DSMEM);

    float *xg0, *xg1, *h1, *h2;
    __nv_bfloat16 *hhi, *hlo, *wghi, *wglo;
    cudaGetSymbolAddress((void**)&xg0,  g_xg0);
    cudaGetSymbolAddress((void**)&xg1,  g_xg1);
    cudaGetSymbolAddress((void**)&h1,   g_h1);
    cudaGetSymbolAddress((void**)&h2,   g_h2);
    cudaGetSymbolAddress((void**)&hhi,  g_hhi);
    cudaGetSymbolAddress((void**)&hlo,  g_hlo);
    cudaGetSymbolAddress((void**)&wghi, g_wghi);
    cudaGetSymbolAddress((void**)&wglo, g_wglo);

    const size_t BH  = (size_t)BATCH * HID;
    const size_t BG  = (size_t)BATCH * G4;
    const size_t WSZ = (size_t)G4 * HID;

    // 0) Pre-split + gather Whh (both layers)
    prep_whh<<<64, 256>>>(w_hh0, w_hh1);

    // 1) XG0 = input[0:640] @ w_ih0^T + biases
    {
        dim3 grid(G4 / BN, TSTEPS * BATCH / BM);
        hmma_gemm<<<grid, NTH>>>(input, w_ih0, IN0, IN0, IN0,
                                 b_ih0, b_hh0, xg0, G4);
    }
    // 2) Layer-0 recurrence
    gates0<<<128, 256>>>(xg0, h1, hhi, hlo);
    for (int t = 1; t < TSTEPS; t++) {
        lstm_step<<<dim3(32, 4), 256, DSMEM>>>(
            wghi, wglo, xg0 + (size_t)t * BG,
            hhi + ((t - 1) & 1) * BH, hlo + ((t - 1) & 1) * BH,
            hhi + (t & 1) * BH,       hlo + (t & 1) * BH,
            h1 + (size_t)t * BH);
    }
    // 3) XG1 = h1 @ w_ih1^T + biases
    {
        dim3 grid(G4 / BN, TSTEPS * BATCH / BM);
        hmma_gemm<<<grid, NTH>>>(h1, w_ih1, HID, HID, HID,
                                 b_ih1, b_hh1, xg1, G4);
    }
    // 4) Layer-1 recurrence
    gates0<<<128, 256>>>(xg1, h2, hhi, hlo);
    for (int t = 1; t < TSTEPS; t++) {
        lstm_step<<<dim3(32, 4), 256, DSMEM>>>(
            wghi + WSZ, wglo + WSZ, xg1 + (size_t)t * BG,
            hhi + ((t - 1) & 1) * BH, hlo + ((t - 1) & 1) * BH,
            hhi + (t & 1) * BH,       hlo + (t & 1) * BH,
            h2 + (size_t)t * BH);
    }
    // 5) Linear head on h2[4]
    head_kernel<<<BATCH, 256>>>(h2 + (size_t)4 * BH, w_out, b_out, out);
}

// round 6
// speedup vs baseline: 1.1036x; 1.1036x over previous
#include <cuda_runtime.h>
#include <cuda_bf16.h>
#include <math.h>
#include <stdint.h>

#define TSTEPS 5
#define BATCH  128
#define IN0    512
#define HID    1024
#define G4     4096
#define OUTD   32

#define BM 128
#define BN 128
#define BK 32
#define NTH 256
#define RS 40            // smem row stride in bf16 (32 data + 8 pad)

// Scratch (device globals; no allocations allowed)
__device__ float g_xg0[TSTEPS * BATCH * G4];
__device__ float g_xg1[TSTEPS * BATCH * G4];
__device__ float g_h1 [TSTEPS * BATCH * HID];
__device__ float g_h2 [TSTEPS * BATCH * HID];
__device__ float g_c  [BATCH * HID];
__device__ __nv_bfloat16 g_hhi[2][BATCH * HID];
__device__ __nv_bfloat16 g_hlo[2][BATCH * HID];
__device__ float g_prt[32 * 4 * BATCH * BN];    // split-K partials, 8 MB
__device__ int   g_ctr[32];                     // zero-init; self-resetting

__device__ __forceinline__ uint32_t smem_u32(const void* p) {
    uint32_t a;
    asm("{ .reg .u64 t; cvta.to.shared.u64 t, %1; cvt.u32.u64 %0, t; }"
        : "=r"(a) : "l"(p));
    return a;
}

#define LDSM_X4(R, addr)                                                     \
    asm volatile("ldmatrix.sync.aligned.m8n8.x4.shared.b16 "                 \
                 "{%0,%1,%2,%3}, [%4];"                                      \
                 : "=r"((R)[0]), "=r"((R)[1]), "=r"((R)[2]), "=r"((R)[3])    \
                 : "r"(addr))
#define LDSM_X2(R, addr)                                                     \
    asm volatile("ldmatrix.sync.aligned.m8n8.x2.shared.b16 {%0,%1}, [%2];"   \
                 : "=r"((R)[0]), "=r"((R)[1]) : "r"(addr))
#define MMA_BF16(D, Ar, Br)                                                  \
    asm volatile("mma.sync.aligned.m16n8k16.row.col.f32.bf16.bf16.f32 "      \
                 "{%0,%1,%2,%3}, {%4,%5,%6,%7}, {%8,%9}, {%0,%1,%2,%3};"     \
                 : "+f"((D)[0]), "+f"((D)[1]), "+f"((D)[2]), "+f"((D)[3])    \
                 : "r"((Ar)[0]), "r"((Ar)[1]), "r"((Ar)[2]), "r"((Ar)[3]),   \
                   "r"((Br)[0]), "r"((Br)[1]))

__device__ __forceinline__ void split_bf16(float f, uint16_t& h, uint16_t& l) {
    __nv_bfloat16 hb = __float2bfloat16(f);
    __nv_bfloat16 lb = __float2bfloat16(f - __bfloat162float(hb));
    h = __bfloat16_as_ushort(hb);
    l = __bfloat16_as_ushort(lb);
}
__device__ __forceinline__ float sigf(float x) { return 1.f / (1.f + expf(-x)); }

// ---------------------------------------------------------------------------
// Bulk tensor-core GEMM (XG precompute): C = A[M,K] @ W[N,K]^T + b1 + b2
// (proven R3 kernel, unchanged)
// ---------------------------------------------------------------------------
__global__ __launch_bounds__(NTH) void hmma_gemm(
    const float* __restrict__ A, const float* __restrict__ W,
    int strideA, int strideW, int ksize,
    const float* __restrict__ b1, const float* __restrict__ b2,
    float* __restrict__ C, int ldc)
{
    __shared__ uint16_t sA[2][BM * RS];
    __shared__ uint16_t sW[2][BN * RS];

    const int tid  = threadIdx.x;
    const int lane = tid & 31;
    const int warp = tid >> 5;
    const int wm   = warp >> 2;
    const int wn   = warp & 3;
    const int row0 = blockIdx.y * BM;
    const int col0 = blockIdx.x * BN;
    const int nch  = ksize / BK;

    const bool isA = (tid < 128);
    const int  t2  = tid & 127;
    const float* src = isA ? (A + (size_t)row0 * strideA)
                           : (W + (size_t)col0 * strideW);
    const int sstr = isA ? strideA : strideW;
    uint16_t* d0 = isA ? sA[0] : sW[0];
    uint16_t* d1 = isA ? sA[1] : sW[1];

    float4 pf[8];
    const uint32_t bA0 = smem_u32(sA[0]);
    const uint32_t bA1 = smem_u32(sA[1]);
    const uint32_t bW0 = smem_u32(sW[0]);
    const uint32_t bW1 = smem_u32(sW[1]);

    float acc[4][4][4];
#pragma unroll
    for (int i = 0; i < 4; i++)
#pragma unroll
        for (int j = 0; j < 4; j++)
#pragma unroll
            for (int v = 0; v < 4; v++) acc[i][j][v] = 0.f;

#pragma unroll
    for (int i = 0; i < 8; i++) {
        int idx = t2 + 128 * i;
        int r = idx >> 3, c4 = idx & 7;
        pf[i] = *(const float4*)(src + (size_t)r * sstr + c4 * 4);
    }

    const int rl  = lane & 7;
    const int s8  = (lane >> 3) & 1;
    const int s16 = (lane >> 4) & 1;

    for (int c = 0; c < nch; c++) {
#pragma unroll
        for (int i = 0; i < 8; i++) {
            int idx = t2 + 128 * i;
            int r = idx >> 3, c4 = idx & 7;
            float f[4] = {pf[i].x, pf[i].y, pf[i].z, pf[i].w};
            uint16_t h[4], l[4];
#pragma unroll
            for (int j = 0; j < 4; j++) split_bf16(f[j], h[j], l[j]);
            int o = r * RS + c4 * 4;
            *(uint2*)(d0 + o) = *(uint2*)h;
            *(uint2*)(d1 + o) = *(uint2*)l;
        }
        __syncthreads();

        if (c + 1 < nch) {
            const int kk = (c + 1) * BK;
#pragma unroll
            for (int i = 0; i < 8; i++) {
                int idx = t2 + 128 * i;
                int r = idx >> 3, c4 = idx & 7;
                pf[i] = *(const float4*)(src + (size_t)r * sstr + kk + c4 * 4);
            }
        }

#pragma unroll
        for (int ks = 0; ks < 2; ks++) {
            const int k0b = (ks * 16 + s8 * 8) * 2;
            const int k0a = (ks * 16 + s16 * 8) * 2;
            uint32_t bh[4][2], bl[4][2];
#pragma unroll
            for (int nt = 0; nt < 4; nt++) {
                uint32_t ro = (uint32_t)(wn * 32 + nt * 8 + rl) * (RS * 2) + k0b;
                LDSM_X2(bh[nt], bW0 + ro);
                LDSM_X2(bl[nt], bW1 + ro);
            }
#pragma unroll
            for (int mt = 0; mt < 4; mt++) {
                uint32_t ro = (uint32_t)(wm * 64 + mt * 16 + rl + s8 * 8) * (RS * 2) + k0a;
                uint32_t ah[4], al[4];
                LDSM_X4(ah, bA0 + ro);
                LDSM_X4(al, bA1 + ro);
#pragma unroll
                for (int nt = 0; nt < 4; nt++) {
                    MMA_BF16(acc[mt][nt], ah, bh[nt]);
                    MMA_BF16(acc[mt][nt], ah, bl[nt]);
                    MMA_BF16(acc[mt][nt], al, bh[nt]);
                }
            }
        }
        __syncthreads();
    }

#pragma unroll
    for (int mt = 0; mt < 4; mt++) {
        int row = row0 + wm * 64 + mt * 16 + (lane >> 2);
#pragma unroll
        for (int nt = 0; nt < 4; nt++) {
            int col = col0 + wn * 32 + nt * 8 + (lane & 3) * 2;
            float bb0 = b1[col] + b2[col];
            float bb1 = b1[col + 1] + b2[col + 1];
            float2 v0 = make_float2(acc[mt][nt][0] + bb0, acc[mt][nt][1] + bb1);
            float2 v1 = make_float2(acc[mt][nt][2] + bb0, acc[mt][nt][3] + bb1);
            *(float2*)(C + (size_t)row * ldc + col) = v0;
            *(float2*)(C + (size_t)(row + 8) * ldc + col) = v1;
        }
    }
}

// ---------------------------------------------------------------------------
// gates0: t=0 step (no recurrent term). Writes c, h fp32, h hi/lo bf16.
// ---------------------------------------------------------------------------
__global__ __launch_bounds__(256) void gates0(
    const float* __restrict__ xg, float* __restrict__ hseq,
    __nv_bfloat16* __restrict__ hhi, __nv_bfloat16* __restrict__ hlo)
{
    int q  = blockIdx.x * 256 + threadIdx.x;
    int b  = q >> 8;
    int j4 = (q & 255) * 4;
    size_t base = (size_t)b * G4 + j4;

    float4 xi = *(const float4*)(xg + base);
    float4 xc = *(const float4*)(xg + base + 2 * HID);
    float4 xo = *(const float4*)(xg + base + 3 * HID);

    float gi[4] = {xi.x, xi.y, xi.z, xi.w};
    float gc[4] = {xc.x, xc.y, xc.z, xc.w};
    float go[4] = {xo.x, xo.y, xo.z, xo.w};
    float cv[4], hv[4];
    uint16_t hh[4], hl[4];
#pragma unroll
    for (int j = 0; j < 4; j++) {
        cv[j] = sigf(gi[j]) * tanhf(gc[j]);
        hv[j] = sigf(go[j]) * tanhf(cv[j]);
        split_bf16(hv[j], hh[j], hl[j]);
    }
    int idx = b * HID + j4;
    *(float4*)(g_c + idx)  = make_float4(cv[0], cv[1], cv[2], cv[3]);
    *(float4*)(hseq + idx) = make_float4(hv[0], hv[1], hv[2], hv[3]);
    *(uint2*)(hhi + idx) = *(uint2*)hh;
    *(uint2*)(hlo + idx) = *(uint2*)hl;
}

// ---------------------------------------------------------------------------
// Fused recurrent step: R3-shaped split-K GEMM with gates in the epilogue.
// grid = (32 unit-blocks, 4 K-slices). CTA tile: 128 batch x 128 gathered cols
// (col n -> gate n/32, unit bx*32 + n%32), K-slice of 256.
// Last CTA per unit-block reduces 4 partials + xg and applies LSTM gates.
// ---------------------------------------------------------------------------
__global__ __launch_bounds__(256) void lstm_step(
    const float* __restrict__ Whh,
    const float* __restrict__ xgt,               // [BATCH][G4] slice for t
    const __nv_bfloat16* __restrict__ hp_hi,
    const __nv_bfloat16* __restrict__ hp_lo,
    __nv_bfloat16* __restrict__ ho_hi,
    __nv_bfloat16* __restrict__ ho_lo,
    float* __restrict__ hseq)
{
    __shared__ uint16_t sA[2][BM * RS];
    __shared__ uint16_t sW[2][BN * RS];
    __shared__ int lastFlag;

    const int tid  = threadIdx.x;
    const int lane = tid & 31;
    const int warp = tid >> 5;
    const int wm   = warp >> 2;
    const int wn   = warp & 3;
    const int bx   = blockIdx.x;                 // unit block (32 units)
    const int ksl  = blockIdx.y;                 // K slice
    const int kbeg = ksl * 256;

    const bool isA = (tid < 128);
    const int  t2  = tid & 127;

    // A: batch row t2, bf16 hi/lo pre-split. W: gathered row t2 from fp32 Whh.
    const __nv_bfloat16* ahi = hp_hi + (size_t)t2 * HID + kbeg;
    const __nv_bfloat16* alo = hp_lo + (size_t)t2 * HID + kbeg;
    const int grow = (t2 >> 5) * HID + bx * 32 + (t2 & 31);
    const float* wsrc = Whh + (size_t)grow * HID + kbeg;

    const uint32_t bA0 = smem_u32(sA[0]);
    const uint32_t bA1 = smem_u32(sA[1]);
    const uint32_t bW0 = smem_u32(sW[0]);
    const uint32_t bW1 = smem_u32(sW[1]);

    float acc[4][4][4];
#pragma unroll
    for (int i = 0; i < 4; i++)
#pragma unroll
        for (int j = 0; j < 4; j++)
#pragma unroll
            for (int v = 0; v < 4; v++) acc[i][j][v] = 0.f;

    uint4 pfu[8];
    // prefetch chunk 0
    if (isA) {
#pragma unroll
        for (int s = 0; s < 4; s++) {
            pfu[s]     = *(const uint4*)(ahi + s * 8);
            pfu[4 + s] = *(const uint4*)(alo + s * 8);
        }
    } else {
#pragma unroll
        for (int s = 0; s < 8; s++)
            ((float4*)pfu)[s] = *(const float4*)(wsrc + s * 4);
    }

    const int rl  = lane & 7;
    const int s8  = (lane >> 3) & 1;
    const int s16 = (lane >> 4) & 1;

    for (int c = 0; c < 8; c++) {
        // store prefetched chunk into smem
        if (isA) {
#pragma unroll
            for (int s = 0; s < 4; s++) {
                *(uint4*)(sA[0] + t2 * RS + s * 8) = pfu[s];
                *(uint4*)(sA[1] + t2 * RS + s * 8) = pfu[4 + s];
            }
        } else {
            const float* f = (const float*)pfu;
#pragma unroll
            for (int g = 0; g < 8; g++) {
                uint16_t h[4], l[4];
#pragma unroll
                for (int j = 0; j < 4; j++) split_bf16(f[g * 4 + j], h[j], l[j]);
                *(uint2*)(sW[0] + t2 * RS + g * 4) = *(uint2*)h;
                *(uint2*)(sW[1] + t2 * RS + g * 4) = *(uint2*)l;
            }
        }
        __syncthreads();

        // prefetch next chunk
        if (c + 1 < 8) {
            const int kk = (c + 1) * BK;
            if (isA) {
#pragma unroll
                for (int s = 0; s < 4; s++) {
                    pfu[s]     = *(const uint4*)(ahi + kk + s * 8);
                    pfu[4 + s] = *(const uint4*)(alo + kk + s * 8);
                }
            } else {
#pragma unroll
                for (int s = 0; s < 8; s++)
                    ((float4*)pfu)[s] = *(const float4*)(wsrc + kk + s * 4);
            }
        }

#pragma unroll
        for (int kk2 = 0; kk2 < 2; kk2++) {
            const int k0b = (kk2 * 16 + s8 * 8) * 2;
            const int k0a = (kk2 * 16 + s16 * 8) * 2;
            uint32_t bh[4][2], bl[4][2];
#pragma unroll
            for (int nt = 0; nt < 4; nt++) {
                uint32_t ro = (uint32_t)(wn * 32 + nt * 8 + rl) * (RS * 2) + k0b;
                LDSM_X2(bh[nt], bW0 + ro);
                LDSM_X2(bl[nt], bW1 + ro);
            }
#pragma unroll
            for (int mt = 0; mt < 4; mt++) {
                uint32_t ro = (uint32_t)(wm * 64 + mt * 16 + rl + s8 * 8) * (RS * 2) + k0a;
                uint32_t ah[4], al[4];
                LDSM_X4(ah, bA0 + ro);
                LDSM_X4(al, bA1 + ro);
#pragma unroll
                for (int nt = 0; nt < 4; nt++) {
                    MMA_BF16(acc[mt][nt], ah, bh[nt]);
                    MMA_BF16(acc[mt][nt], ah, bl[nt]);
                    MMA_BF16(acc[mt][nt], al, bh[nt]);
                }
            }
        }
        __syncthreads();
    }

    // ---- store partial tile ----
    float* myp = g_prt + ((size_t)(bx * 4 + ksl) << 14);
#pragma unroll
    for (int mt = 0; mt < 4; mt++) {
        int row = wm * 64 + mt * 16 + (lane >> 2);
#pragma unroll
        for (int nt = 0; nt < 4; nt++) {
            int col = wn * 32 + nt * 8 + (lane & 3) * 2;
            *(float2*)(myp + row * BN + col) =
                make_float2(acc[mt][nt][0], acc[mt][nt][1]);
            *(float2*)(myp + (row + 8) * BN + col) =
                make_float2(acc[mt][nt][2], acc[mt][nt][3]);
        }
    }

    __threadfence();
    __syncthreads();
    if (tid == 0) lastFlag = (atomicAdd(&g_ctr[bx], 1) == 3);
    __syncthreads();

    if (lastFlag) {
        __threadfence();
        const float* p0 = g_prt + ((size_t)(bx * 4 + 0) << 14);
        const float* p1 = g_prt + ((size_t)(bx * 4 + 1) << 14);
        const float* p2 = g_prt + ((size_t)(bx * 4 + 2) << 14);
        const float* p3 = g_prt + ((size_t)(bx * 4 + 3) << 14);
#pragma unroll
        for (int i = 0; i < 16; i++) {
            int p   = i * 256 + tid;           // 0..4095
            int row = p >> 5;                  // batch 0..127
            int ui  = p & 31;
            int j   = bx * 32 + ui;
            int o   = row * BN;
            float gi = p0[o + ui]      + p1[o + ui]      + p2[o + ui]      + p3[o + ui];
            float gf = p0[o + 32 + ui] + p1[o + 32 + ui] + p2[o + 32 + ui] + p3[o + 32 + ui];
            float gg = p0[o + 64 + ui] + p1[o + 64 + ui] + p2[o + 64 + ui] + p3[o + 64 + ui];
            float go = p0[o + 96 + ui] + p1[o + 96 + ui] + p2[o + 96 + ui] + p3[o + 96 + ui];
            size_t xb = (size_t)row * G4 + j;
            gi += xgt[xb];
            gf += xgt[xb + HID];
            gg += xgt[xb + 2 * HID];
            go += xgt[xb + 3 * HID];
            int idx = row * HID + j;
            float cp = g_c[idx];
            float cn = sigf(gf) * cp + sigf(gi) * tanhf(gg);
            float hn = sigf(go) * tanhf(cn);
            g_c[idx]  = cn;
            hseq[idx] = hn;
            uint16_t hh, hl;
            split_bf16(hn, hh, hl);
            ho_hi[idx] = __ushort_as_bfloat16(hh);
            ho_lo[idx] = __ushort_as_bfloat16(hl);
        }
        __syncthreads();
        if (tid == 0) atomicExch(&g_ctr[bx], 0);   // self-reset for next launch
    }
}

// ---------------------------------------------------------------------------
// Head: out[b,o] = dot(h2[4][b,:], Wout[o,:]) + bout[o]
// ---------------------------------------------------------------------------
__global__ __launch_bounds__(256) void head_kernel(
    const float* __restrict__ hfin,
    const float* __restrict__ Wout, const float* __restrict__ bout,
    float* __restrict__ out)
{
    __shared__ float hs[HID];
    __shared__ float red[8][32];
    int b = blockIdx.x;
    for (int i = threadIdx.x; i < HID; i += 256) hs[i] = hfin[(size_t)b * HID + i];
    __syncthreads();

    int o     = threadIdx.x % 32;
    int chunk = threadIdx.x / 32;
    float s = 0.f;
    const float* wrow = Wout + (size_t)o * HID;
#pragma unroll 4
    for (int k = chunk * 128; k < chunk * 128 + 128; k++)
        s = fmaf(hs[k], wrow[k], s);
    red[chunk][o] = s;
    __syncthreads();

    if (threadIdx.x < 32) {
        float t = 0.f;
#pragma unroll
        for (int ch = 0; ch < 8; ch++) t += red[ch][threadIdx.x];
        out[(size_t)b * OUTD + threadIdx.x] = t + bout[threadIdx.x];
    }
}

// ---------------------------------------------------------------------------
// Host launcher (13 launches)
// ---------------------------------------------------------------------------
extern "C" void kernel_launch(void* const* d_in, const int* in_sizes, int n_in,
                              void* d_out, int out_size)
{
    const float* input = (const float*)d_in[0];
    const float* w_ih0 = (const float*)d_in[1];
    const float* w_hh0 = (const float*)d_in[2];
    const float* b_ih0 = (const float*)d_in[3];
    const float* b_hh0 = (const float*)d_in[4];
    const float* w_ih1 = (const float*)d_in[5];
    const float* w_hh1 = (const float*)d_in[6];
    const float* b_ih1 = (const float*)d_in[7];
    const float* b_hh1 = (const float*)d_in[8];
    const float* w_out = (const float*)d_in[9];
    const float* b_out = (const float*)d_in[10];
    float* out = (float*)d_out;

    float *xg0, *xg1, *h1, *h2;
    __nv_bfloat16 *hhi, *hlo;
    cudaGetSymbolAddress((void**)&xg0, g_xg0);
    cudaGetSymbolAddress((void**)&xg1, g_xg1);
    cudaGetSymbolAddress((void**)&h1,  g_h1);
    cudaGetSymbolAddress((void**)&h2,  g_h2);
    cudaGetSymbolAddress((void**)&hhi, g_hhi);
    cudaGetSymbolAddress((void**)&hlo, g_hlo);

    const size_t BH = (size_t)BATCH * HID;
    const size_t BG = (size_t)BATCH * G4;

    // 1) XG0 = input[0:640] @ w_ih0^T + biases
    {
        dim3 grid(G4 / BN, TSTEPS * BATCH / BM);
        hmma_gemm<<<grid, NTH>>>(input, w_ih0, IN0, IN0, IN0,
                                 b_ih0, b_hh0, xg0, G4);
    }
    // 2) Layer-0 recurrence (fused split-K GEMM + gates per step)
    gates0<<<128, 256>>>(xg0, h1, hhi, hlo);
    for (int t = 1; t < TSTEPS; t++) {
        lstm_step<<<dim3(32, 4), 256>>>(
            w_hh0, xg0 + (size_t)t * BG,
            hhi + ((t - 1) & 1) * BH, hlo + ((t - 1) & 1) * BH,
            hhi + (t & 1) * BH,       hlo + (t & 1) * BH,
            h1 + (size_t)t * BH);
    }
    // 3) XG1 = h1 @ w_ih1^T + biases
    {
        dim3 grid(G4 / BN, TSTEPS * BATCH / BM);
        hmma_gemm<<<grid, NTH>>>(h1, w_ih1, HID, HID, HID,
                                 b_ih1, b_hh1, xg1, G4);
    }
    // 4) Layer-1 recurrence
    gates0<<<128, 256>>>(xg1, h2, hhi, hlo);
    for (int t = 1; t < TSTEPS; t++) {
        lstm_step<<<dim3(32, 4), 256>>>(
            w_hh1, xg1 + (size_t)t * BG,
            hhi + ((t - 1) & 1) * BH, hlo + ((t - 1) & 1) * BH,
            hhi + (t & 1) * BH,       hlo + (t & 1) * BH,
            h2 + (size_t)t * BH);
    }
    // 5) Linear head on h2[4]
    head_kernel<<<BATCH, 256>>>(h2 + (size_t)4 * BH, w_out, b_out, out);
}

// round 7
// speedup vs baseline: 1.3550x; 1.2278x over previous
#include <cuda_runtime.h>
#include <cuda_bf16.h>
#include <math.h>
#include <stdint.h>

#define TSTEPS 5
#define BATCH  128
#define IN0    512
#define HID    1024
#define G4     4096
#define OUTD   32
#define KSPLIT 4

#define BM 128
#define BN 128
#define BK 32
#define NTH 256
#define RS 40            // smem row stride in bf16 (32 data + 8 pad)

// Scratch (device globals; no allocations allowed)
__device__ float g_xg0[TSTEPS * BATCH * G4];
__device__ float g_xg1[TSTEPS * BATCH * G4];
__device__ float g_h1 [TSTEPS * BATCH * HID];
__device__ float g_h2 [TSTEPS * BATCH * HID];
__device__ float g_c  [BATCH * HID];
__device__ __nv_bfloat16 g_hhi[2][BATCH * HID];
__device__ __nv_bfloat16 g_hlo[2][BATCH * HID];
__device__ float g_prt[KSPLIT * BATCH * G4];    // split-K partials, 8 MB

__device__ __forceinline__ uint32_t smem_u32(const void* p) {
    uint32_t a;
    asm("{ .reg .u64 t; cvta.to.shared.u64 t, %1; cvt.u32.u64 %0, t; }"
        : "=r"(a) : "l"(p));
    return a;
}

#define LDSM_X4(R, addr)                                                     \
    asm volatile("ldmatrix.sync.aligned.m8n8.x4.shared.b16 "                 \
                 "{%0,%1,%2,%3}, [%4];"                                      \
                 : "=r"((R)[0]), "=r"((R)[1]), "=r"((R)[2]), "=r"((R)[3])    \
                 : "r"(addr))
#define LDSM_X2(R, addr)                                                     \
    asm volatile("ldmatrix.sync.aligned.m8n8.x2.shared.b16 {%0,%1}, [%2];"   \
                 : "=r"((R)[0]), "=r"((R)[1]) : "r"(addr))
#define MMA_BF16(D, Ar, Br)                                                  \
    asm volatile("mma.sync.aligned.m16n8k16.row.col.f32.bf16.bf16.f32 "      \
                 "{%0,%1,%2,%3}, {%4,%5,%6,%7}, {%8,%9}, {%0,%1,%2,%3};"     \
                 : "+f"((D)[0]), "+f"((D)[1]), "+f"((D)[2]), "+f"((D)[3])    \
                 : "r"((Ar)[0]), "r"((Ar)[1]), "r"((Ar)[2]), "r"((Ar)[3]),   \
                   "r"((Br)[0]), "r"((Br)[1]))

__device__ __forceinline__ void split_bf16(float f, uint16_t& h, uint16_t& l) {
    __nv_bfloat16 hb = __float2bfloat16(f);
    __nv_bfloat16 lb = __float2bfloat16(f - __bfloat162float(hb));
    h = __bfloat16_as_ushort(hb);
    l = __bfloat16_as_ushort(lb);
}
__device__ __forceinline__ float sigf(float x) { return 1.f / (1.f + expf(-x)); }
// Interleaved gate layout: gathered col q <-> natural row (q&3)*HID + (q>>2)
__device__ __forceinline__ int icol(int q) { return (q & 3) * HID + (q >> 2); }

// ---------------------------------------------------------------------------
// Bulk tensor-core GEMM (XG precompute), interleaved output columns:
// C[r][q] = A[r,:] . W[icol(q),:] + b1[icol(q)] + b2[icol(q)]
// 1 sync per chunk (LDG(c+1) -> MMA(c) -> STS(c+1) -> sync).
// ---------------------------------------------------------------------------
__global__ __launch_bounds__(NTH) void hmma_gemm(
    const float* __restrict__ A, const float* __restrict__ W,
    int strideA, int strideW, int ksize,
    const float* __restrict__ b1, const float* __restrict__ b2,
    float* __restrict__ C, int ldc)
{
    __shared__ uint16_t sA[2][2][BM * RS];   // [buf][hi/lo]
    __shared__ uint16_t sW[2][2][BN * RS];

    const int tid  = threadIdx.x;
    const int lane = tid & 31;
    const int warp = tid >> 5;
    const int wm   = warp >> 2;
    const int wn   = warp & 3;
    const int row0 = blockIdx.y * BM;
    const int col0 = blockIdx.x * BN;
    const int nch  = ksize / BK;

    const bool isA = (tid < 128);
    const int  t2  = tid & 127;

    float acc[4][4][4];
#pragma unroll
    for (int i = 0; i < 4; i++)
#pragma unroll
        for (int j = 0; j < 4; j++)
#pragma unroll
            for (int v = 0; v < 4; v++) acc[i][j][v] = 0.f;

    float4 pf[8];
#pragma unroll
    for (int i = 0; i < 8; i++) {
        int idx = t2 + 128 * i;
        int r = idx >> 3, c4 = idx & 7;
        const float* src = isA ? (A + (size_t)(row0 + r) * strideA)
                               : (W + (size_t)icol(col0 + r) * strideW);
        pf[i] = *(const float4*)(src + c4 * 4);
    }
    {
        uint16_t* d0 = isA ? sA[0][0] : sW[0][0];
        uint16_t* d1 = isA ? sA[0][1] : sW[0][1];
#pragma unroll
        for (int i = 0; i < 8; i++) {
            int idx = t2 + 128 * i;
            int r = idx >> 3, c4 = idx & 7;
            float f[4] = {pf[i].x, pf[i].y, pf[i].z, pf[i].w};
            uint16_t h[4], l[4];
#pragma unroll
            for (int j = 0; j < 4; j++) split_bf16(f[j], h[j], l[j]);
            int o = r * RS + c4 * 4;
            *(uint2*)(d0 + o) = *(uint2*)h;
            *(uint2*)(d1 + o) = *(uint2*)l;
        }
    }
    __syncthreads();

    const int rl  = lane & 7;
    const int s8  = (lane >> 3) & 1;
    const int s16 = (lane >> 4) & 1;

    for (int c = 0; c < nch; c++) {
        const int buf = c & 1;
        if (c + 1 < nch) {
            const int kk = (c + 1) * BK;
#pragma unroll
            for (int i = 0; i < 8; i++) {
                int idx = t2 + 128 * i;
                int r = idx >> 3, c4 = idx & 7;
                const float* src = isA ? (A + (size_t)(row0 + r) * strideA)
                                       : (W + (size_t)icol(col0 + r) * strideW);
                pf[i] = *(const float4*)(src + kk + c4 * 4);
            }
        }

        const uint32_t aH = smem_u32(sA[buf][0]);
        const uint32_t aL = smem_u32(sA[buf][1]);
        const uint32_t wH = smem_u32(sW[buf][0]);
        const uint32_t wL = smem_u32(sW[buf][1]);
#pragma unroll
        for (int ks = 0; ks < 2; ks++) {
            const int k0b = (ks * 16 + s8 * 8) * 2;
            const int k0a = (ks * 16 + s16 * 8) * 2;
            uint32_t bh[4][2], bl[4][2];
#pragma unroll
            for (int nt = 0; nt < 4; nt++) {
                uint32_t ro = (uint32_t)(wn * 32 + nt * 8 + rl) * (RS * 2) + k0b;
                LDSM_X2(bh[nt], wH + ro);
                LDSM_X2(bl[nt], wL + ro);
            }
#pragma unroll
            for (int mt = 0; mt < 4; mt++) {
                uint32_t ro = (uint32_t)(wm * 64 + mt * 16 + rl + s8 * 8) * (RS * 2) + k0a;
                uint32_t ah[4], al[4];
                LDSM_X4(ah, aH + ro);
                LDSM_X4(al, aL + ro);
#pragma unroll
                for (int nt = 0; nt < 4; nt++) {
                    MMA_BF16(acc[mt][nt], ah, bh[nt]);
                    MMA_BF16(acc[mt][nt], ah, bl[nt]);
                    MMA_BF16(acc[mt][nt], al, bh[nt]);
                }
            }
        }

        if (c + 1 < nch) {
            uint16_t* d0 = isA ? sA[buf ^ 1][0] : sW[buf ^ 1][0];
            uint16_t* d1 = isA ? sA[buf ^ 1][1] : sW[buf ^ 1][1];
#pragma unroll
            for (int i = 0; i < 8; i++) {
                int idx = t2 + 128 * i;
                int r = idx >> 3, c4 = idx & 7;
                float f[4] = {pf[i].x, pf[i].y, pf[i].z, pf[i].w};
                uint16_t h[4], l[4];
#pragma unroll
                for (int j = 0; j < 4; j++) split_bf16(f[j], h[j], l[j]);
                int o = r * RS + c4 * 4;
                *(uint2*)(d0 + o) = *(uint2*)h;
                *(uint2*)(d1 + o) = *(uint2*)l;
            }
        }
        __syncthreads();
    }

#pragma unroll
    for (int mt = 0; mt < 4; mt++) {
        int row = row0 + wm * 64 + mt * 16 + (lane >> 2);
#pragma unroll
        for (int nt = 0; nt < 4; nt++) {
            int col = col0 + wn * 32 + nt * 8 + (lane & 3) * 2;
            float bb0 = b1[icol(col)] + b2[icol(col)];
            float bb1 = b1[icol(col + 1)] + b2[icol(col + 1)];
            float2 v0 = make_float2(acc[mt][nt][0] + bb0, acc[mt][nt][1] + bb1);
            float2 v1 = make_float2(acc[mt][nt][2] + bb0, acc[mt][nt][3] + bb1);
            *(float2*)(C + (size_t)row * ldc + col) = v0;
            *(float2*)(C + (size_t)(row + 8) * ldc + col) = v1;
        }
    }
}

// ---------------------------------------------------------------------------
// Step GEMM: partial[ksl][b][q] = h_prev[b,:kslice] . Whh[icol(q),:kslice]
// tile 128(M) x 64(N), split-K=4 (slices of 256) -> grid (64, 4), 128 threads.
// A-operand pre-split bf16 hi/lo. 1 sync per chunk.
// ---------------------------------------------------------------------------
__global__ __launch_bounds__(128) void step_gemm(
    const float* __restrict__ Whh,
    const __nv_bfloat16* __restrict__ hp_hi,
    const __nv_bfloat16* __restrict__ hp_lo)
{
    __shared__ uint16_t sA[2][2][BM * RS];   // [buf][hi/lo] 128 rows
    __shared__ uint16_t sW[2][2][64 * RS];   // [buf][hi/lo] 64 rows

    const int tid  = threadIdx.x;       // 0..127
    const int lane = tid & 31;
    const int warp = tid >> 5;          // 0..3
    const int wm   = warp >> 1;         // 0..1 -> M half (64)
    const int wn   = warp & 1;          // 0..1 -> N half (32)
    const int bx   = blockIdx.x;        // n-tile (64 cols)
    const int ksl  = blockIdx.y;
    const int kbeg = ksl * (HID / KSPLIT);   // 256

    // A prefetch: row = tid (batch), 32 k-elems hi+lo
    const __nv_bfloat16* ah = hp_hi + (size_t)tid * HID + kbeg;
    const __nv_bfloat16* al = hp_lo + (size_t)tid * HID + kbeg;
    // W prefetch: wrow = tid>>1 (0..63), whalf = tid&1 (16 k-elems fp32)
    const int wrow  = tid >> 1;
    const int whalf = tid & 1;
    const float* ws = Whh + (size_t)icol(bx * 64 + wrow) * HID + kbeg + whalf * 16;

    float acc[4][4][4];
#pragma unroll
    for (int mt = 0; mt < 4; mt++)
#pragma unroll
        for (int nt = 0; nt < 4; nt++)
#pragma unroll
            for (int v = 0; v < 4; v++) acc[mt][nt][v] = 0.f;

    uint4  pA[8];        // 4 hi + 4 lo
    float4 pW[4];        // 16 fp32

#pragma unroll
    for (int s = 0; s < 4; s++) {
        pA[s]     = *(const uint4*)(ah + s * 8);
        pA[4 + s] = *(const uint4*)(al + s * 8);
        pW[s]     = *(const float4*)(ws + s * 4);
    }
    // STS chunk 0
    {
#pragma unroll
        for (int s = 0; s < 4; s++) {
            *(uint4*)(sA[0][0] + tid * RS + s * 8) = pA[s];
            *(uint4*)(sA[0][1] + tid * RS + s * 8) = pA[4 + s];
        }
        const float* f = (const float*)pW;
        uint16_t h[16], l[16];
#pragma unroll
        for (int j = 0; j < 16; j++) split_bf16(f[j], h[j], l[j]);
#pragma unroll
        for (int s = 0; s < 2; s++) {
            *(uint4*)(sW[0][0] + wrow * RS + whalf * 16 + s * 8) = ((uint4*)h)[s];
            *(uint4*)(sW[0][1] + wrow * RS + whalf * 16 + s * 8) = ((uint4*)l)[s];
        }
    }
    __syncthreads();

    const int rl  = lane & 7;
    const int s8  = (lane >> 3) & 1;
    const int s16 = (lane >> 4) & 1;
    const int nch = (HID / KSPLIT) / BK;   // 8

    for (int c = 0; c < nch; c++) {
        const int buf = c & 1;
        if (c + 1 < nch) {
            const int kk = (c + 1) * BK;
#pragma unroll
            for (int s = 0; s < 4; s++) {
                pA[s]     = *(const uint4*)(ah + kk + s * 8);
                pA[4 + s] = *(const uint4*)(al + kk + s * 8);
                pW[s]     = *(const float4*)(ws + kk + s * 4);
            }
        }

        const uint32_t aH = smem_u32(sA[buf][0]);
        const uint32_t aL = smem_u32(sA[buf][1]);
        const uint32_t wH = smem_u32(sW[buf][0]);
        const uint32_t wL = smem_u32(sW[buf][1]);
#pragma unroll
        for (int ks = 0; ks < 2; ks++) {
            const int k0b = (ks * 16 + s8 * 8) * 2;
            const int k0a = (ks * 16 + s16 * 8) * 2;
            uint32_t bh[4][2], bl[4][2];
#pragma unroll
            for (int nt = 0; nt < 4; nt++) {
                uint32_t ro = (uint32_t)(wn * 32 + nt * 8 + rl) * (RS * 2) + k0b;
                LDSM_X2(bh[nt], wH + ro);
                LDSM_X2(bl[nt], wL + ro);
            }
#pragma unroll
            for (int mt = 0; mt < 4; mt++) {
                uint32_t ro = (uint32_t)(wm * 64 + mt * 16 + rl + s8 * 8) * (RS * 2) + k0a;
                uint32_t ahf[4], alf[4];
                LDSM_X4(ahf, aH + ro);
                LDSM_X4(alf, aL + ro);
#pragma unroll
                for (int nt = 0; nt < 4; nt++) {
                    MMA_BF16(acc[mt][nt], ahf, bh[nt]);
                    MMA_BF16(acc[mt][nt], ahf, bl[nt]);
                    MMA_BF16(acc[mt][nt], alf, bh[nt]);
                }
            }
        }

        if (c + 1 < nch) {
#pragma unroll
            for (int s = 0; s < 4; s++) {
                *(uint4*)(sA[buf ^ 1][0] + tid * RS + s * 8) = pA[s];
                *(uint4*)(sA[buf ^ 1][1] + tid * RS + s * 8) = pA[4 + s];
            }
            const float* f = (const float*)pW;
            uint16_t h[16], l[16];
#pragma unroll
            for (int j = 0; j < 16; j++) split_bf16(f[j], h[j], l[j]);
#pragma unroll
            for (int s = 0; s < 2; s++) {
                *(uint4*)(sW[buf ^ 1][0] + wrow * RS + whalf * 16 + s * 8) = ((uint4*)h)[s];
                *(uint4*)(sW[buf ^ 1][1] + wrow * RS + whalf * 16 + s * 8) = ((uint4*)l)[s];
            }
        }
        __syncthreads();
    }

    // partial store
    float* myp = g_prt + (size_t)ksl * BATCH * G4;
#pragma unroll
    for (int mt = 0; mt < 4; mt++) {
        int row = wm * 64 + mt * 16 + (lane >> 2);
#pragma unroll
        for (int nt = 0; nt < 4; nt++) {
            int col = bx * 64 + wn * 32 + nt * 8 + (lane & 3) * 2;
            *(float2*)(myp + (size_t)row * G4 + col) =
                make_float2(acc[mt][nt][0], acc[mt][nt][1]);
            *(float2*)(myp + (size_t)(row + 8) * G4 + col) =
                make_float2(acc[mt][nt][2], acc[mt][nt][3]);
        }
    }
}

// ---------------------------------------------------------------------------
// Gates reduction: g = xg + sum_ksl partial; interleaved layout (float4 = one
// unit's i,f,g,o). Thread handles 2 units. Writes c, h fp32, h hi/lo bf16.
// ---------------------------------------------------------------------------
__global__ __launch_bounds__(256) void gates_red(
    const float* __restrict__ xg, float* __restrict__ hseq,
    __nv_bfloat16* __restrict__ hhi, __nv_bfloat16* __restrict__ hlo)
{
    int q  = blockIdx.x * 256 + threadIdx.x;   // 0..65535
    int b  = q >> 9;
    int j2 = (q & 511) * 2;
    size_t cb = (size_t)b * G4 + j2 * 4;

    float4 v0 = *(const float4*)(xg + cb);
    float4 v1 = *(const float4*)(xg + cb + 4);
#pragma unroll
    for (int s = 0; s < KSPLIT; s++) {
        const float* P = g_prt + (size_t)s * BATCH * G4 + cb;
        float4 p0 = *(const float4*)(P);
        float4 p1 = *(const float4*)(P + 4);
        v0.x += p0.x; v0.y += p0.y; v0.z += p0.z; v0.w += p0.w;
        v1.x += p1.x; v1.y += p1.y; v1.z += p1.z; v1.w += p1.w;
    }

    int idx = b * HID + j2;
    float2 cp = *(const float2*)(g_c + idx);
    float cn0 = sigf(v0.y) * cp.x + sigf(v0.x) * tanhf(v0.z);
    float hn0 = sigf(v0.w) * tanhf(cn0);
    float cn1 = sigf(v1.y) * cp.y + sigf(v1.x) * tanhf(v1.z);
    float hn1 = sigf(v1.w) * tanhf(cn1);

    *(float2*)(g_c + idx)  = make_float2(cn0, cn1);
    *(float2*)(hseq + idx) = make_float2(hn0, hn1);
    uint16_t h0, l0, h1, l1;
    split_bf16(hn0, h0, l0);
    split_bf16(hn1, h1, l1);
    *(uint32_t*)(hhi + idx) = (uint32_t)h0 | ((uint32_t)h1 << 16);
    *(uint32_t*)(hlo + idx) = (uint32_t)l0 | ((uint32_t)l1 << 16);
}

// ---------------------------------------------------------------------------
// gates0: t=0 (no recurrent term), interleaved xg.
// ---------------------------------------------------------------------------
__global__ __launch_bounds__(256) void gates0(
    const float* __restrict__ xg, float* __restrict__ hseq,
    __nv_bfloat16* __restrict__ hhi, __nv_bfloat16* __restrict__ hlo)
{
    int q  = blockIdx.x * 256 + threadIdx.x;
    int b  = q >> 9;
    int j2 = (q & 511) * 2;
    size_t cb = (size_t)b * G4 + j2 * 4;

    float4 v0 = *(const float4*)(xg + cb);
    float4 v1 = *(const float4*)(xg + cb + 4);

    float cn0 = sigf(v0.x) * tanhf(v0.z);
    float hn0 = sigf(v0.w) * tanhf(cn0);
    float cn1 = sigf(v1.x) * tanhf(v1.z);
    float hn1 = sigf(v1.w) * tanhf(cn1);

    int idx = b * HID + j2;
    *(float2*)(g_c + idx)  = make_float2(cn0, cn1);
    *(float2*)(hseq + idx) = make_float2(hn0, hn1);
    uint16_t h0, l0, h1, l1;
    split_bf16(hn0, h0, l0);
    split_bf16(hn1, h1, l1);
    *(uint32_t*)(hhi + idx) = (uint32_t)h0 | ((uint32_t)h1 << 16);
    *(uint32_t*)(hlo + idx) = (uint32_t)l0 | ((uint32_t)l1 << 16);
}

// ---------------------------------------------------------------------------
// Head: out[b,o] = dot(h2[4][b,:], Wout[o,:]) + bout[o]
// ---------------------------------------------------------------------------
__global__ __launch_bounds__(256) void head_kernel(
    const float* __restrict__ hfin,
    const float* __restrict__ Wout, const float* __restrict__ bout,
    float* __restrict__ out)
{
    __shared__ float hs[HID];
    __shared__ float red[8][32];
    int b = blockIdx.x;
    for (int i = threadIdx.x; i < HID; i += 256) hs[i] = hfin[(size_t)b * HID + i];
    __syncthreads();

    int o     = threadIdx.x % 32;
    int chunk = threadIdx.x / 32;
    float s = 0.f;
    const float* wrow = Wout + (size_t)o * HID;
#pragma unroll 4
    for (int k = chunk * 128; k < chunk * 128 + 128; k++)
        s = fmaf(hs[k], wrow[k], s);
    red[chunk][o] = s;
    __syncthreads();

    if (threadIdx.x < 32) {
        float t = 0.f;
#pragma unroll
        for (int ch = 0; ch < 8; ch++) t += red[ch][threadIdx.x];
        out[(size_t)b * OUTD + threadIdx.x] = t + bout[threadIdx.x];
    }
}

// ---------------------------------------------------------------------------
// Host launcher
// ---------------------------------------------------------------------------
extern "C" void kernel_launch(void* const* d_in, const int* in_sizes, int n_in,
                              void* d_out, int out_size)
{
    const float* input = (const float*)d_in[0];
    const float* w_ih0 = (const float*)d_in[1];
    const float* w_hh0 = (const float*)d_in[2];
    const float* b_ih0 = (const float*)d_in[3];
    const float* b_hh0 = (const float*)d_in[4];
    const float* w_ih1 = (const float*)d_in[5];
    const float* w_hh1 = (const float*)d_in[6];
    const float* b_ih1 = (const float*)d_in[7];
    const float* b_hh1 = (const float*)d_in[8];
    const float* w_out = (const float*)d_in[9];
    const float* b_out = (const float*)d_in[10];
    float* out = (float*)d_out;

    float *xg0, *xg1, *h1, *h2;
    __nv_bfloat16 *hhi, *hlo;
    cudaGetSymbolAddress((void**)&xg0, g_xg0);
    cudaGetSymbolAddress((void**)&xg1, g_xg1);
    cudaGetSymbolAddress((void**)&h1,  g_h1);
    cudaGetSymbolAddress((void**)&h2,  g_h2);
    cudaGetSymbolAddress((void**)&hhi, g_hhi);
    cudaGetSymbolAddress((void**)&hlo, g_hlo);

    const size_t BH = (size_t)BATCH * HID;
    const size_t BG = (size_t)BATCH * G4;

    // 1) XG0 = input[0:640] @ w_ih0^T (interleaved cols) + biases
    {
        dim3 grid(G4 / BN, TSTEPS * BATCH / BM);
        hmma_gemm<<<grid, NTH>>>(input, w_ih0, IN0, IN0, IN0,
                                 b_ih0, b_hh0, xg0, G4);
    }
    // 2) Layer-0 recurrence
    gates0<<<256, 256>>>(xg0, h1, hhi, hlo);
    for (int t = 1; t < TSTEPS; t++) {
        step_gemm<<<dim3(64, KSPLIT), 128>>>(
            w_hh0, hhi + ((t - 1) & 1) * BH, hlo + ((t - 1) & 1) * BH);
        gates_red<<<256, 256>>>(xg0 + (size_t)t * BG, h1 + (size_t)t * BH,
                                hhi + (t & 1) * BH, hlo + (t & 1) * BH);
    }
    // 3) XG1 = h1 @ w_ih1^T (interleaved cols) + biases
    {
        dim3 grid(G4 / BN, TSTEPS * BATCH / BM);
        hmma_gemm<<<grid, NTH>>>(h1, w_ih1, HID, HID, HID,
                                 b_ih1, b_hh1, xg1, G4);
    }
    // 4) Layer-1 recurrence
    gates0<<<256, 256>>>(xg1, h2, hhi, hlo);
    for (int t = 1; t < TSTEPS; t++) {
        step_gemm<<<dim3(64, KSPLIT), 128>>>(
            w_hh1, hhi + ((t - 1) & 1) * BH, hlo + ((t - 1) & 1) * BH);
        gates_red<<<256, 256>>>(xg1 + (size_t)t * BG, h2 + (size_t)t * BH,
                                hhi + (t & 1) * BH, hlo + (t & 1) * BH);
    }
    // 5) Linear head on h2[4]
    head_kernel<<<BATCH, 256>>>(h2 + (size_t)4 * BH, w_out, b_out, out);
}